// round 10
// baseline (speedup 1.0000x reference)
#include <cuda_runtime.h>
#include <cuda_fp16.h>
#include <math.h>
#include <stdint.h>

// Problem dims
constexpr int kT  = 4096;   // timesteps
constexpr int kD  = 1024;   // input dim
constexpr int kH  = 2048;   // hidden
constexpr int kH3 = 3 * kH; // 6144

// GRU kernel: 148 blocks x 1024 threads; each block owns the SAME j-slice of BOTH GRUs
// (nj = 14 for blocks 0..123, 13 for 124..147; 124*14 + 24*13 = 2048).
// Per GRU: R = 3*nj rows. GRU0 rows 0..31 in smem, rows 32..R-1 in regs (warps 0..REG0-1).
// GRU1 rows 0..S1-1 in smem, rows S1..R-1 in regs (warps REG0..31).
// Total smem rows = 32 + S1 <= 52; reg rows = 32 (exactly 1 per warp, 32 regs/thread).
constexpr int SMAX     = 52;
constexpr int GRU_SMEM = kH * 2 + SMAX * kH * 2 + 2 * 48 * 4;  // h + weights + s_preA/B

// -------- scratch (static device globals; no allocation allowed) --------
__device__ float  g_xp[2][(size_t)kT * kH3];    // input projections (fp32)
__device__ __half g_w16[2][(size_t)kH3 * kH];   // fp16 W_hh
__device__ __half g_wih16[2][(size_t)kH3 * kD]; // fp16 W_ih
__device__ __half g_x16[2][(size_t)kT * kD];    // fp16 x
__device__ __align__(16) __half g_h16[2][2][kH]; // ping-pong hidden state [buf][gru][H]
__device__ float  g_act[256];                   // fc1 activations
__device__ unsigned g_ctr[2];                   // monotonic barrier counters (reset by gemm)

// ---------------- conversions (2 launches so gru_seq stays at my index 3) ------------
__global__ void convert_whh_both(const float* __restrict__ W1, const float* __restrict__ W2)
{
    const size_t i = (size_t)blockIdx.x * blockDim.x + threadIdx.x;   // kH3*kH/2
    const float2* src = (const float2*)(blockIdx.y ? W2 : W1);
    float2 v = src[i];
    ((__half2*)g_w16[blockIdx.y])[i] = __floats2half2_rn(v.x, v.y);
}
__global__ void convert_misc(const float* __restrict__ Wih1, const float* __restrict__ Wih2,
                             const float* __restrict__ x1,   const float* __restrict__ x2)
{
    const size_t i = (size_t)blockIdx.x * blockDim.x + threadIdx.x;
    const int gru = blockIdx.y;
    if (blockIdx.z == 0) {                      // W_ih: kH3*kD/2 elements
        const float2* src = (const float2*)(gru ? Wih2 : Wih1);
        float2 v = src[i];
        ((__half2*)g_wih16[gru])[i] = __floats2half2_rn(v.x, v.y);
    } else {                                    // x: kT*kD/2 elements (guard)
        if (i >= (size_t)kT * kD / 2) return;
        const float2* src = (const float2*)(gru ? x2 : x1);
        float2 v = src[i];
        ((__half2*)g_x16[gru])[i] = __floats2half2_rn(v.x, v.y);
    }
}

// ---------------- Phase A: xp = x @ W_ih^T + b_ih  (fp16 HFMA2) ----------------
constexpr int GBM = 128, GBN = 64, GBK = 32;

__global__ void __launch_bounds__(256, 2) gemm_xp16(
    const float* __restrict__ bih1, const float* __restrict__ bih2)
{
    // reset gru barrier counters for this graph replay (runs before gru_seq in-stream)
    if (blockIdx.x == 0 && blockIdx.y == 0 && blockIdx.z == 0 && threadIdx.x == 0) {
        g_ctr[0] = 0; g_ctr[1] = 0;
    }

    const int gru = blockIdx.z;
    const __half* __restrict__ X = g_x16[gru];
    const __half* __restrict__ W = g_wih16[gru];
    const float*  __restrict__ b = gru ? bih2 : bih1;
    float* __restrict__ xp = g_xp[gru];

    __shared__ __half2 As[GBK / 2][GBM + 1];
    __shared__ __half2 Bs[GBK / 2][GBN + 1];

    const int tid = threadIdx.x;
    const int tx = tid & 15, ty = tid >> 4;
    const int t0 = blockIdx.y * GBM;
    const int j0 = blockIdx.x * GBN;

    float acc[8][4] = {};

    for (int k0 = 0; k0 < kD; k0 += GBK) {
        #pragma unroll
        for (int r = 0; r < 2; r++) {
            int i = tid + r * 256;
            int t = i >> 2;
            int kc = (i & 3) * 8;
            uint4 v = *(const uint4*)(X + (size_t)(t0 + t) * kD + k0 + kc);
            const __half2* hv = (const __half2*)&v;
            int k2b = kc >> 1;
            As[k2b + 0][t] = hv[0]; As[k2b + 1][t] = hv[1];
            As[k2b + 2][t] = hv[2]; As[k2b + 3][t] = hv[3];
        }
        {
            int j = tid >> 2;
            int kc = (tid & 3) * 8;
            uint4 v = *(const uint4*)(W + (size_t)(j0 + j) * kD + k0 + kc);
            const __half2* hv = (const __half2*)&v;
            int k2b = kc >> 1;
            Bs[k2b + 0][j] = hv[0]; Bs[k2b + 1][j] = hv[1];
            Bs[k2b + 2][j] = hv[2]; Bs[k2b + 3][j] = hv[3];
        }
        __syncthreads();

        __half2 hz = __float2half2_rn(0.f);
        __half2 hacc[8][4];
        #pragma unroll
        for (int i = 0; i < 8; i++)
            #pragma unroll
            for (int l = 0; l < 4; l++) hacc[i][l] = hz;

        #pragma unroll
        for (int k2 = 0; k2 < GBK / 2; k2++) {
            __half2 a[8], bb[4];
            #pragma unroll
            for (int i = 0; i < 8; i++) a[i] = As[k2][ty * 8 + i];
            #pragma unroll
            for (int l = 0; l < 4; l++) bb[l] = Bs[k2][tx * 4 + l];
            #pragma unroll
            for (int i = 0; i < 8; i++)
                #pragma unroll
                for (int l = 0; l < 4; l++)
                    hacc[i][l] = __hfma2(a[i], bb[l], hacc[i][l]);
        }
        #pragma unroll
        for (int i = 0; i < 8; i++)
            #pragma unroll
            for (int l = 0; l < 4; l++) {
                float2 f = __half22float2(hacc[i][l]);
                acc[i][l] += f.x + f.y;
            }
        __syncthreads();
    }

    const int jj = j0 + tx * 4;
    float4 bv = *(const float4*)(b + jj);
    #pragma unroll
    for (int i = 0; i < 8; i++) {
        float4 v = make_float4(acc[i][0] + bv.x, acc[i][1] + bv.y,
                               acc[i][2] + bv.z, acc[i][3] + bv.w);
        __stcs((float4*)(xp + (size_t)(t0 + ty * 8 + i) * kH3 + jj), v);
    }
}

// ---------------- 8-half dot (fp16 mul-acc, fp32 flush) ----------------
__device__ __forceinline__ float dot8(uint4 wv, uint4 hh)
{
    __half2 t = __hmul2(*(const __half2*)&wv.x, *(const __half2*)&hh.x);
    t = __hfma2(*(const __half2*)&wv.y, *(const __half2*)&hh.y, t);
    t = __hfma2(*(const __half2*)&wv.z, *(const __half2*)&hh.z, t);
    t = __hfma2(*(const __half2*)&wv.w, *(const __half2*)&hh.w, t);
    float2 f = __half22float2(t);
    return f.x + f.y;
}

__device__ __forceinline__ float sigf(float x) { return 1.f / (1.f + expf(-x)); }

// ---------------- Phase B: persistent dual-GRU, phases interleaved ----------------
__global__ void __launch_bounds__(1024, 1) gru_seq(
    const float* __restrict__ bhh1, const float* __restrict__ bhh2)
{
    extern __shared__ unsigned char smem_raw[];
    __half* sh_h   = (__half*)smem_raw;                          // 2048 halves
    __half* sh_w   = (__half*)(smem_raw + kH * 2);               // up to 52 rows
    float*  s_preA = (float*)(smem_raw + kH * 2 + SMAX * kH * 2);
    float*  s_preB = s_preA + 48;

    const int blk = blockIdx.x;                 // 0..147
    const int nj    = (blk < 124) ? 14 : 13;
    const int jbase = (blk < 124) ? blk * 14 : 124 * 14 + (blk - 124) * 13;
    const int R    = 3 * nj;                    // 42 or 39
    const int REG0 = R - 32;                    // GRU0 reg-row count (10 or 7)
    const int S1   = 2 * R - 64;                // GRU1 smem-row count (20 or 14)

    const int tid = threadIdx.x;
    const int w = tid >> 5, lane = tid & 31;

    // ---- fill smem: slots 0..31 = GRU0 rows 0..31; slots 32..32+S1-1 = GRU1 rows ----
    {
        const int nslots = 32 + S1;
        for (int idx = tid; idx < nslots * 256; idx += 1024) {
            int slot = idx >> 8, u = idx & 255;
            int g  = (slot >= 32) ? 1 : 0;
            int lr = g ? (slot - 32) : slot;
            int lj = lr / 3, gate = lr - 3 * lj;
            ((uint4*)sh_w)[idx] =
                ((const uint4*)(g_w16[g] + ((size_t)gate * kH + jbase + lj) * kH))[u];
        }
    }

    // ---- this warp's single register row ----
    const int rg  = (w < REG0) ? 0 : 1;
    const int rlr = (w < REG0) ? (32 + w) : (R - 32 + w);
    uint4 wreg[8];
    {
        int lj = rlr / 3, gate = rlr - 3 * lj;
        const uint4* p = (const uint4*)(g_w16[rg] + ((size_t)gate * kH + jbase + lj) * kH);
        #pragma unroll
        for (int u = 0; u < 8; u++) wreg[u] = __ldcg(p + u * 32 + lane);
    }

    if (tid < nj) {
        g_h16[0][0][jbase + tid] = __float2half(0.f);
        g_h16[0][1][jbase + tid] = __float2half(0.f);
    }

    // gate warps: 31 -> GRU0, 30 -> GRU1; lanes 0..nj-1, one j each
    const bool gwA = (w == 31) && (lane < nj);
    const bool gwB = (w == 30) && (lane < nj);
    const int jg = jbase + lane;
    float br = 0.f, bz = 0.f, bn = 0.f;               // t-invariant biases
    if (gwA) { br = bhh1[jg]; bz = bhh1[kH + jg]; bn = bhh1[2 * kH + jg]; }
    if (gwB) { br = bhh2[jg]; bz = bhh2[kH + jg]; bn = bhh2[2 * kH + jg]; }
    float h_prev = 0.f;    // gate lane's fp32 h[j] — THE unique writer carries it (R8 scheme)

    // init arrivals (h0 + smem fill published)
    __syncthreads();
    if (tid == 0) {
        __threadfence();
        atomicAdd(&g_ctr[0], 1u);
        atomicAdd(&g_ctr[1], 1u);
    }

    const uint4* hv = (const uint4*)sh_h;
    const uint4* pwA = (const uint4*)sh_w + w * 256;          // GRU0 smem row w
    const uint4* pwB = (const uint4*)sh_w + (32 + w) * 256;   // GRU1 smem row w (if w<S1)

    for (int t = 0; t < kT; t++) {
        const int cur = t & 1, nxt = cur ^ 1;
        const unsigned tgt = 148u * (t + 1);

        // prefetch xp for both gate warps (t-known, long before use)
        float xr = 0.f, xz = 0.f, xn = 0.f;
        if (gwA || gwB) {
            const float* xpt = g_xp[(w == 30) ? 1 : 0] + (size_t)t * kH3;
            xr = __ldcs(xpt + jg);
            xz = __ldcs(xpt + kH + jg);
            xn = __ldcs(xpt + 2 * kH + jg);
        }

        // ===== wait A(t): all blocks published hA(t) =====
        if (tid == 0) {
            while (*(volatile unsigned*)&g_ctr[0] < tgt) {}
            __threadfence();                     // acquire: fresh view for the stage LDGs
        }
        __syncthreads();

        // stage hA
        if (tid < 256)
            ((uint4*)sh_h)[tid] = ((const uint4*)g_h16[cur][0])[tid];
        __syncthreads();

        // dots A: smem row w (all warps) + reg row (warps < REG0)
        {
            float a0 = 0.f, a1 = 0.f;
            #pragma unroll
            for (int c = 0; c < 8; c++) {
                uint4 hh = hv[c * 32 + lane];
                a0 += dot8(pwA[c * 32 + lane], hh);
                if (w < REG0) a1 += dot8(wreg[c], hh);
            }
            #pragma unroll
            for (int off = 16; off; off >>= 1) {
                a0 += __shfl_xor_sync(0xffffffffu, a0, off);
                a1 += __shfl_xor_sync(0xffffffffu, a1, off);
            }
            if (lane == 0) {
                s_preA[w] = a0;
                if (w < REG0) s_preA[32 + w] = a1;
            }
        }
        __syncthreads();

        // gate A (warp 31) runs concurrently with the ctrB poll (thread 0)
        if (w == 31) {
            if (lane < nj) {
                float r = sigf(xr + s_preA[3 * lane + 0] + br);
                float z = sigf(xz + s_preA[3 * lane + 1] + bz);
                float n = tanhf(xn + r * (s_preA[3 * lane + 2] + bn));
                float hnew = (1.f - z) * n + z * h_prev;
                h_prev = hnew;
                g_h16[nxt][0][jg] = __float2half(hnew);
            }
            __threadfence();
            __syncwarp();
            if (lane == 0) atomicAdd(&g_ctr[0], 1u);
        }
        if (tid == 0) {
            while (*(volatile unsigned*)&g_ctr[1] < tgt) {}
            __threadfence();
        }
        __syncthreads();

        // stage hB
        if (tid < 256)
            ((uint4*)sh_h)[tid] = ((const uint4*)g_h16[cur][1])[tid];
        __syncthreads();

        // dots B: smem row 32+w (warps < S1) + reg row (warps >= REG0)
        {
            float a0 = 0.f, a1 = 0.f;
            #pragma unroll
            for (int c = 0; c < 8; c++) {
                uint4 hh = hv[c * 32 + lane];
                if (w < S1) a0 += dot8(pwB[c * 32 + lane], hh);
                if (w >= REG0) a1 += dot8(wreg[c], hh);
            }
            #pragma unroll
            for (int off = 16; off; off >>= 1) {
                a0 += __shfl_xor_sync(0xffffffffu, a0, off);
                a1 += __shfl_xor_sync(0xffffffffu, a1, off);
            }
            if (lane == 0) {
                if (w < S1) s_preB[w] = a0;
                if (w >= REG0) s_preB[R - 32 + w] = a1;
            }
        }
        __syncthreads();

        // gate B (warp 30); next iteration's ctrA poll overlaps it
        if (w == 30) {
            if (lane < nj) {
                float r = sigf(xr + s_preB[3 * lane + 0] + br);
                float z = sigf(xz + s_preB[3 * lane + 1] + bz);
                float n = tanhf(xn + r * (s_preB[3 * lane + 2] + bn));
                float hnew = (1.f - z) * n + z * h_prev;
                h_prev = hnew;
                g_h16[nxt][1][jg] = __float2half(hnew);
            }
            __threadfence();
            __syncwarp();
            if (lane == 0) atomicAdd(&g_ctr[1], 1u);
        }
    }
    // final h in g_h16[0] (t=4095: cur=1 -> nxt=0)
}

// ---------------- Phase C1: fc1 (parallel over 32 blocks) ----------------
__global__ void head_fc1(const float* __restrict__ fc1_w, const float* __restrict__ fc1_b)
{
    const int r = blockIdx.x * 8 + (threadIdx.x >> 5);
    const int lane = threadIdx.x & 31;
    const __half* __restrict__ h0 = g_h16[0][0];
    const __half* __restrict__ h1 = g_h16[0][1];
    const float* __restrict__ wr = fc1_w + (size_t)r * (2 * kH);

    float s = 0.f;
    #pragma unroll 4
    for (int i = 0; i < 32; i++) {
        int k = i * 128 + lane * 4;
        float4 wv = *(const float4*)(wr + k);
        const __half* hs = (k < kH) ? (h0 + k) : (h1 + (k - kH));
        uint2 hh = *(const uint2*)hs;
        float2 f0 = __half22float2(*(const __half2*)&hh.x);
        float2 f1 = __half22float2(*(const __half2*)&hh.y);
        s = fmaf(wv.x, f0.x, s); s = fmaf(wv.y, f0.y, s);
        s = fmaf(wv.z, f1.x, s); s = fmaf(wv.w, f1.y, s);
    }
    #pragma unroll
    for (int off = 16; off; off >>= 1) s += __shfl_down_sync(0xffffffffu, s, off);
    if (lane == 0) g_act[r] = fmaxf(s + fc1_b[r], 0.f);
}

// ---------------- Phase C2: fc2 + log_softmax ----------------
__global__ void head_fc2(const float* __restrict__ fc2_w, const float* __restrict__ fc2_b,
                         float* __restrict__ out)
{
    __shared__ float logits[3];
    const int g = threadIdx.x >> 5, lane = threadIdx.x & 31;
    float s = 0.f;
    const float* wr = fc2_w + g * 256;
    #pragma unroll
    for (int i = 0; i < 2; i++) {
        int k = lane * 8 + i * 4;
        float4 wv = *(const float4*)(wr + k);
        float4 av = *(const float4*)(g_act + k);
        s = fmaf(wv.x, av.x, s); s = fmaf(wv.y, av.y, s);
        s = fmaf(wv.z, av.z, s); s = fmaf(wv.w, av.w, s);
    }
    #pragma unroll
    for (int off = 16; off; off >>= 1) s += __shfl_down_sync(0xffffffffu, s, off);
    if (lane == 0) logits[g] = s + fc2_b[g];
    __syncthreads();
    if (threadIdx.x == 0) {
        float m = fmaxf(logits[0], fmaxf(logits[1], logits[2]));
        float lse = m + logf(expf(logits[0] - m) + expf(logits[1] - m) + expf(logits[2] - m));
        out[0] = logits[0] - lse;
        out[1] = logits[1] - lse;
        out[2] = logits[2] - lse;
    }
}

// ---------------- launch (gru_seq at my index 3 for ncu capture) ----------------
extern "C" void kernel_launch(void* const* d_in, const int* in_sizes, int n_in,
                              void* d_out, int out_size)
{
    const float* x1   = (const float*)d_in[0];
    const float* x2   = (const float*)d_in[1];
    const float* Wih1 = (const float*)d_in[2];
    const float* Whh1 = (const float*)d_in[3];
    const float* bih1 = (const float*)d_in[4];
    const float* bhh1 = (const float*)d_in[5];
    const float* Wih2 = (const float*)d_in[6];
    const float* Whh2 = (const float*)d_in[7];
    const float* bih2 = (const float*)d_in[8];
    const float* bhh2 = (const float*)d_in[9];
    const float* fc1w = (const float*)d_in[10];
    const float* fc1b = (const float*)d_in[11];
    const float* fc2w = (const float*)d_in[12];
    const float* fc2b = (const float*)d_in[13];
    float* out = (float*)d_out;

    cudaFuncSetAttribute(gru_seq, cudaFuncAttributeMaxDynamicSharedMemorySize, GRU_SMEM);

    convert_whh_both<<<dim3(kH3 * kH / 2 / 1024, 2), 1024>>>(Whh1, Whh2);        // 0
    convert_misc<<<dim3(kH3 * kD / 2 / 1024, 2, 2), 1024>>>(Wih1, Wih2, x1, x2); // 1

    dim3 gA(kH3 / GBN, kT / GBM, 2);
    gemm_xp16<<<gA, 256>>>(bih1, bih2);                                          // 2 (resets g_ctr)

    gru_seq<<<148, 1024, GRU_SMEM>>>(bhh1, bhh2);                                // 3 (profiled)

    head_fc1<<<32, 256>>>(fc1w, fc1b);                                           // 4
    head_fc2<<<1, 96>>>(fc2w, fc2b, out);                                        // 5
}

// round 11
// speedup vs baseline: 1.2828x; 1.2828x over previous
#include <cuda_runtime.h>
#include <cuda_fp16.h>
#include <math.h>
#include <stdint.h>

// Problem dims
constexpr int kT  = 4096;   // timesteps
constexpr int kD  = 1024;   // input dim
constexpr int kH  = 2048;   // hidden
constexpr int kH3 = 3 * kH; // 6144

// GRU kernel: 148 blocks x 1024 threads, block owns same j-slice of BOTH GRUs.
// Warps 0..15 run GRU0, warps 16..31 run GRU1 — fully independent chains
// (own named barrier, own global counter). Per half: R = 3*nj rows
// (42 or 39); first S = R-16 rows in smem (26/23), last 16 rows in registers
// (exactly 1 per warp, 32 regs/thread).
constexpr int SMAX_HALF = 26;                     // smem row slots per GRU
constexpr int GRU_SMEM  = 2 * kH * 2              // two h staging buffers
                        + 2 * SMAX_HALF * kH * 2  // 52 weight rows
                        + 2 * 48 * 4;             // s_pre per half
                                                  // = 8192 + 212992 + 384 = 221568

// -------- scratch (static device globals; no allocation allowed) --------
__device__ float  g_xp[2][(size_t)kT * kH3];    // input projections (fp32)
__device__ __half g_w16[2][(size_t)kH3 * kH];   // fp16 W_hh
__device__ __half g_wih16[2][(size_t)kH3 * kD]; // fp16 W_ih
__device__ __half g_x16[2][(size_t)kT * kD];    // fp16 x
__device__ __align__(16) __half g_h16[2][2][kH]; // ping-pong hidden state [buf][gru][H]
__device__ float  g_act[256];                   // fc1 activations
__device__ unsigned g_ctr[2];                   // monotonic barrier counters (reset by gemm)

// ---------------- conversions (2 launches so gru_seq stays at my index 3) ------------
__global__ void convert_whh_both(const float* __restrict__ W1, const float* __restrict__ W2)
{
    const size_t i = (size_t)blockIdx.x * blockDim.x + threadIdx.x;   // kH3*kH/2
    const float2* src = (const float2*)(blockIdx.y ? W2 : W1);
    float2 v = src[i];
    ((__half2*)g_w16[blockIdx.y])[i] = __floats2half2_rn(v.x, v.y);
}
__global__ void convert_misc(const float* __restrict__ Wih1, const float* __restrict__ Wih2,
                             const float* __restrict__ x1,   const float* __restrict__ x2)
{
    const size_t i = (size_t)blockIdx.x * blockDim.x + threadIdx.x;
    const int gru = blockIdx.y;
    if (blockIdx.z == 0) {                      // W_ih: kH3*kD/2 elements
        const float2* src = (const float2*)(gru ? Wih2 : Wih1);
        float2 v = src[i];
        ((__half2*)g_wih16[gru])[i] = __floats2half2_rn(v.x, v.y);
    } else {                                    // x: kT*kD/2 elements (guard)
        if (i >= (size_t)kT * kD / 2) return;
        const float2* src = (const float2*)(gru ? x2 : x1);
        float2 v = src[i];
        ((__half2*)g_x16[gru])[i] = __floats2half2_rn(v.x, v.y);
    }
}

// ---------------- Phase A: xp = x @ W_ih^T + b_ih  (fp16 HFMA2) ----------------
constexpr int GBM = 128, GBN = 64, GBK = 32;

__global__ void __launch_bounds__(256, 2) gemm_xp16(
    const float* __restrict__ bih1, const float* __restrict__ bih2)
{
    // reset gru barrier counters for this graph replay (runs before gru_seq in-stream)
    if (blockIdx.x == 0 && blockIdx.y == 0 && blockIdx.z == 0 && threadIdx.x == 0) {
        g_ctr[0] = 0; g_ctr[1] = 0;
    }

    const int gru = blockIdx.z;
    const __half* __restrict__ X = g_x16[gru];
    const __half* __restrict__ W = g_wih16[gru];
    const float*  __restrict__ b = gru ? bih2 : bih1;
    float* __restrict__ xp = g_xp[gru];

    __shared__ __half2 As[GBK / 2][GBM + 1];
    __shared__ __half2 Bs[GBK / 2][GBN + 1];

    const int tid = threadIdx.x;
    const int tx = tid & 15, ty = tid >> 4;
    const int t0 = blockIdx.y * GBM;
    const int j0 = blockIdx.x * GBN;

    float acc[8][4] = {};

    for (int k0 = 0; k0 < kD; k0 += GBK) {
        #pragma unroll
        for (int r = 0; r < 2; r++) {
            int i = tid + r * 256;
            int t = i >> 2;
            int kc = (i & 3) * 8;
            uint4 v = *(const uint4*)(X + (size_t)(t0 + t) * kD + k0 + kc);
            const __half2* hv = (const __half2*)&v;
            int k2b = kc >> 1;
            As[k2b + 0][t] = hv[0]; As[k2b + 1][t] = hv[1];
            As[k2b + 2][t] = hv[2]; As[k2b + 3][t] = hv[3];
        }
        {
            int j = tid >> 2;
            int kc = (tid & 3) * 8;
            uint4 v = *(const uint4*)(W + (size_t)(j0 + j) * kD + k0 + kc);
            const __half2* hv = (const __half2*)&v;
            int k2b = kc >> 1;
            Bs[k2b + 0][j] = hv[0]; Bs[k2b + 1][j] = hv[1];
            Bs[k2b + 2][j] = hv[2]; Bs[k2b + 3][j] = hv[3];
        }
        __syncthreads();

        __half2 hz = __float2half2_rn(0.f);
        __half2 hacc[8][4];
        #pragma unroll
        for (int i = 0; i < 8; i++)
            #pragma unroll
            for (int l = 0; l < 4; l++) hacc[i][l] = hz;

        #pragma unroll
        for (int k2 = 0; k2 < GBK / 2; k2++) {
            __half2 a[8], bb[4];
            #pragma unroll
            for (int i = 0; i < 8; i++) a[i] = As[k2][ty * 8 + i];
            #pragma unroll
            for (int l = 0; l < 4; l++) bb[l] = Bs[k2][tx * 4 + l];
            #pragma unroll
            for (int i = 0; i < 8; i++)
                #pragma unroll
                for (int l = 0; l < 4; l++)
                    hacc[i][l] = __hfma2(a[i], bb[l], hacc[i][l]);
        }
        #pragma unroll
        for (int i = 0; i < 8; i++)
            #pragma unroll
            for (int l = 0; l < 4; l++) {
                float2 f = __half22float2(hacc[i][l]);
                acc[i][l] += f.x + f.y;
            }
        __syncthreads();
    }

    const int jj = j0 + tx * 4;
    float4 bv = *(const float4*)(b + jj);
    #pragma unroll
    for (int i = 0; i < 8; i++) {
        float4 v = make_float4(acc[i][0] + bv.x, acc[i][1] + bv.y,
                               acc[i][2] + bv.z, acc[i][3] + bv.w);
        __stcs((float4*)(xp + (size_t)(t0 + ty * 8 + i) * kH3 + jj), v);
    }
}

// ---------------- 8-half dot (fp16 mul-acc, fp32 flush) ----------------
__device__ __forceinline__ float dot8(uint4 wv, uint4 hh)
{
    __half2 t = __hmul2(*(const __half2*)&wv.x, *(const __half2*)&hh.x);
    t = __hfma2(*(const __half2*)&wv.y, *(const __half2*)&hh.y, t);
    t = __hfma2(*(const __half2*)&wv.z, *(const __half2*)&hh.z, t);
    t = __hfma2(*(const __half2*)&wv.w, *(const __half2*)&hh.w, t);
    float2 f = __half22float2(t);
    return f.x + f.y;
}

__device__ __forceinline__ float sigf(float x) { return 1.f / (1.f + expf(-x)); }

// named barrier for one 512-thread half
__device__ __forceinline__ void half_bar(int g)
{
    asm volatile("bar.sync %0, 512;" :: "r"(1 + g) : "memory");
}

// ---------------- Phase B: persistent dual-GRU, warp-specialized halves ----------------
__global__ void __launch_bounds__(1024, 1) gru_seq(
    const float* __restrict__ bhh1, const float* __restrict__ bhh2)
{
    extern __shared__ unsigned char smem_raw[];
    __half* sh_hbase = (__half*)smem_raw;                            // 2 x 2048 halves
    __half* sh_w     = (__half*)(smem_raw + 2 * kH * 2);             // 52 weight rows
    float*  s_prebase= (float*)(smem_raw + 2 * kH * 2 + 2 * SMAX_HALF * kH * 2);

    const int blk = blockIdx.x;                 // 0..147
    const int nj    = (blk < 124) ? 14 : 13;
    const int jbase = (blk < 124) ? blk * 14 : 124 * 14 + (blk - 124) * 13;
    const int R = 3 * nj;                       // 42 or 39
    const int S = R - 16;                       // smem rows per half (26 or 23)

    const int tid  = threadIdx.x;
    const int g    = tid >> 9;                  // which GRU this warp serves
    const int lt   = tid & 511;                 // thread id within the half
    const int w    = lt >> 5;                   // warp id within the half (0..15)
    const int lane = tid & 31;

    __half* sh_h  = sh_hbase + g * kH;
    float*  s_pre = s_prebase + g * 48;
    const float* __restrict__ bhh = g ? bhh2 : bhh1;
    const float* __restrict__ xp  = g_xp[g];
    const __half* __restrict__ W16 = g_w16[g];

    // ---- fill this half's smem rows (slots g*26 + lr, lr < S) ----
    for (int idx = lt; idx < S * 256; idx += 512) {
        int lr = idx >> 8, u = idx & 255;
        int lj = lr / 3, gate = lr - 3 * lj;
        ((uint4*)sh_w)[(g * SMAX_HALF + lr) * 256 + u] =
            ((const uint4*)(W16 + ((size_t)gate * kH + jbase + lj) * kH))[u];
    }

    // ---- this warp's single register row: lr = S + w (S..R-1) ----
    uint4 wreg[8];
    {
        int lr = S + w;
        int lj = lr / 3, gate = lr - 3 * lj;
        const uint4* p = (const uint4*)(W16 + ((size_t)gate * kH + jbase + lj) * kH);
        #pragma unroll
        for (int u = 0; u < 8; u++) wreg[u] = __ldcg(p + u * 32 + lane);
    }

    if (lt < nj) g_h16[0][g][jbase + lt] = __float2half(0.f);

    // gate warp: last warp of the half (w == 15), lanes 0..nj-1
    const bool gw = (w == 15) && (lane < nj);
    const int jg = jbase + lane;
    float br = 0.f, bz = 0.f, bn = 0.f;
    if (gw) { br = bhh[jg]; bz = bhh[kH + jg]; bn = bhh[2 * kH + jg]; }
    float h_prev = 0.f;      // gate lane's fp32 h[j] (unique writer carries it)

    // publish init (h0 + this block ready) — one arrival per counter per block
    __syncthreads();
    if (tid == 0) {
        __threadfence();
        atomicAdd(&g_ctr[0], 1u);
        atomicAdd(&g_ctr[1], 1u);
    }

    const uint4* hv  = (const uint4*)sh_h;
    const uint4* pw0 = (const uint4*)sh_w + (g * SMAX_HALF + w) * 256;
    const uint4* pw1 = (const uint4*)sh_w + (g * SMAX_HALF + 16 + w) * 256;

    for (int t = 0; t < kT; t++) {
        const int cur = t & 1, nxt = cur ^ 1;

        // xp prefetch (t-known; long before use)
        float xr = 0.f, xz = 0.f, xn = 0.f;
        if (gw) {
            const float* xpt = xp + (size_t)t * kH3;
            xr = __ldcs(xpt + jg);
            xz = __ldcs(xpt + kH + jg);
            xn = __ldcs(xpt + 2 * kH + jg);
        }

        // wait: all blocks published h(t) for this GRU
        if (lt == 0) {
            const unsigned tgt = 148u * (t + 1);
            while (*(volatile unsigned*)&g_ctr[g] < tgt) {}
        }
        half_bar(g);

        // stage h (L2-fresh; 256 threads of this half)
        if (lt < 256)
            ((uint4*)sh_h)[lt] = __ldcg((const uint4*)g_h16[cur][g] + lt);
        half_bar(g);

        // dots: smem row w, smem row 16+w (if < S), reg row S+w
        float a0 = 0.f, a1 = 0.f, a2 = 0.f;
        const bool has2 = (16 + w) < S;
        #pragma unroll
        for (int c = 0; c < 8; c++) {
            uint4 hh = hv[c * 32 + lane];
            a0 += dot8(pw0[c * 32 + lane], hh);
            if (has2) a1 += dot8(pw1[c * 32 + lane], hh);
            a2 += dot8(wreg[c], hh);
        }
        #pragma unroll
        for (int off = 16; off; off >>= 1) {
            a0 += __shfl_xor_sync(0xffffffffu, a0, off);
            a1 += __shfl_xor_sync(0xffffffffu, a1, off);
            a2 += __shfl_xor_sync(0xffffffffu, a2, off);
        }
        if (lane == 0) {
            s_pre[w] = a0;
            if (has2) s_pre[16 + w] = a1;
            s_pre[S + w] = a2;
        }
        half_bar(g);

        // gate math + publish (gate warp only; other warps loop to the poll)
        if (w == 15) {
            if (lane < nj) {
                float r = sigf(xr + s_pre[3 * lane + 0] + br);
                float z = sigf(xz + s_pre[3 * lane + 1] + bz);
                float n = tanhf(xn + r * (s_pre[3 * lane + 2] + bn));
                float hnew = (1.f - z) * n + z * h_prev;
                h_prev = hnew;
                g_h16[nxt][g][jg] = __float2half(hnew);
            }
            __threadfence();
            __syncwarp();
            if (lane == 0) atomicAdd(&g_ctr[g], 1u);
        }
    }
    // final h in g_h16[0] (t=4095: cur=1 -> nxt=0)
}

// ---------------- Phase C1: fc1 (parallel over 32 blocks) ----------------
__global__ void head_fc1(const float* __restrict__ fc1_w, const float* __restrict__ fc1_b)
{
    const int r = blockIdx.x * 8 + (threadIdx.x >> 5);
    const int lane = threadIdx.x & 31;
    const __half* __restrict__ h0 = g_h16[0][0];
    const __half* __restrict__ h1 = g_h16[0][1];
    const float* __restrict__ wr = fc1_w + (size_t)r * (2 * kH);

    float s = 0.f;
    #pragma unroll 4
    for (int i = 0; i < 32; i++) {
        int k = i * 128 + lane * 4;
        float4 wv = *(const float4*)(wr + k);
        const __half* hs = (k < kH) ? (h0 + k) : (h1 + (k - kH));
        uint2 hh = *(const uint2*)hs;
        float2 f0 = __half22float2(*(const __half2*)&hh.x);
        float2 f1 = __half22float2(*(const __half2*)&hh.y);
        s = fmaf(wv.x, f0.x, s); s = fmaf(wv.y, f0.y, s);
        s = fmaf(wv.z, f1.x, s); s = fmaf(wv.w, f1.y, s);
    }
    #pragma unroll
    for (int off = 16; off; off >>= 1) s += __shfl_down_sync(0xffffffffu, s, off);
    if (lane == 0) g_act[r] = fmaxf(s + fc1_b[r], 0.f);
}

// ---------------- Phase C2: fc2 + log_softmax ----------------
__global__ void head_fc2(const float* __restrict__ fc2_w, const float* __restrict__ fc2_b,
                         float* __restrict__ out)
{
    __shared__ float logits[3];
    const int g = threadIdx.x >> 5, lane = threadIdx.x & 31;
    float s = 0.f;
    const float* wr = fc2_w + g * 256;
    #pragma unroll
    for (int i = 0; i < 2; i++) {
        int k = lane * 8 + i * 4;
        float4 wv = *(const float4*)(wr + k);
        float4 av = *(const float4*)(g_act + k);
        s = fmaf(wv.x, av.x, s); s = fmaf(wv.y, av.y, s);
        s = fmaf(wv.z, av.z, s); s = fmaf(wv.w, av.w, s);
    }
    #pragma unroll
    for (int off = 16; off; off >>= 1) s += __shfl_down_sync(0xffffffffu, s, off);
    if (lane == 0) logits[g] = s + fc2_b[g];
    __syncthreads();
    if (threadIdx.x == 0) {
        float m = fmaxf(logits[0], fmaxf(logits[1], logits[2]));
        float lse = m + logf(expf(logits[0] - m) + expf(logits[1] - m) + expf(logits[2] - m));
        out[0] = logits[0] - lse;
        out[1] = logits[1] - lse;
        out[2] = logits[2] - lse;
    }
}

// ---------------- launch (gru_seq at my index 3 for ncu capture) ----------------
extern "C" void kernel_launch(void* const* d_in, const int* in_sizes, int n_in,
                              void* d_out, int out_size)
{
    const float* x1   = (const float*)d_in[0];
    const float* x2   = (const float*)d_in[1];
    const float* Wih1 = (const float*)d_in[2];
    const float* Whh1 = (const float*)d_in[3];
    const float* bih1 = (const float*)d_in[4];
    const float* bhh1 = (const float*)d_in[5];
    const float* Wih2 = (const float*)d_in[6];
    const float* Whh2 = (const float*)d_in[7];
    const float* bih2 = (const float*)d_in[8];
    const float* bhh2 = (const float*)d_in[9];
    const float* fc1w = (const float*)d_in[10];
    const float* fc1b = (const float*)d_in[11];
    const float* fc2w = (const float*)d_in[12];
    const float* fc2b = (const float*)d_in[13];
    float* out = (float*)d_out;

    cudaFuncSetAttribute(gru_seq, cudaFuncAttributeMaxDynamicSharedMemorySize, GRU_SMEM);

    convert_whh_both<<<dim3(kH3 * kH / 2 / 1024, 2), 1024>>>(Whh1, Whh2);        // 0
    convert_misc<<<dim3(kH3 * kD / 2 / 1024, 2, 2), 1024>>>(Wih1, Wih2, x1, x2); // 1

    dim3 gA(kH3 / GBN, kT / GBM, 2);
    gemm_xp16<<<gA, 256>>>(bih1, bih2);                                          // 2 (resets g_ctr)

    gru_seq<<<148, 1024, GRU_SMEM>>>(bhh1, bhh2);                                // 3 (profiled)

    head_fc1<<<32, 256>>>(fc1w, fc1b);                                           // 4
    head_fc2<<<1, 96>>>(fc2w, fc2b, out);                                        // 5
}